// round 2
// baseline (speedup 1.0000x reference)
#include <cuda_runtime.h>
#include <math.h>

#define DCH   128
#define BE    1024
#define NF    128
#define NS    32768

// Dynamic smem layout (floats):
//  A: max(S0 stride12, S2 stride36) = 128*36 = 4608
//  B: max(S1 stride20, S3 stride68) = 128*68 = 8704
#define A_OFF   0
#define A_SIZE  (128*36)
#define B_OFF   (A_OFF + A_SIZE)
#define B_SIZE  (128*68)
#define XF_OFF  (B_OFF + B_SIZE)
#define VS_OFF  (XF_OFF + 128)
#define SMEM_FLOATS (VS_OFF + 128)
#define SMEM_BYTES  (SMEM_FLOATS * 4)

__device__ __forceinline__ float leaky(float v) { return v > 0.f ? v : 0.2f * v; }

// Transposed conv (k=4, s=2, p=1), JAX conv_transpose (no kernel flip):
//   y[2j]   = sum_ci x[j-1]*w0 + x[j]*w2
//   y[2j+1] = sum_ci x[j]  *w1 + x[j+1]*w3
// Weight prefetched one ci ahead; x rows read as float4 chunks.
template <int LIN, int SIN, int SOUT>
__device__ __forceinline__ void tconv(
    const float* __restrict__ W, const float* __restrict__ bias,
    const float* __restrict__ xin, float* __restrict__ yout,
    int co, bool act)
{
    constexpr int LOUT = 2 * LIN;
    constexpr int NC   = LIN / 4;
    float acc[LOUT];
    const float bv = bias[co];
#pragma unroll
    for (int l = 0; l < LOUT; ++l) acc[l] = bv;

    const float* wp = W + co * 4;           // W[(ci*128+co)*4 + h]
    float4 w = *(const float4*)wp;

#pragma unroll 1
    for (int ci = 0; ci < DCH; ++ci) {
        float4 wn = w;
        if (ci + 1 < DCH) wn = *(const float4*)(wp + (ci + 1) * (DCH * 4));
        const float4* xr = (const float4*)(xin + ci * SIN);
        float4 c = xr[0];
        float prev = 0.f;
#pragma unroll
        for (int m = 0; m < NC; ++m) {
            float4 nchunk = make_float4(0.f, 0.f, 0.f, 0.f);
            if (m + 1 < NC) nchunk = xr[m + 1];
            float nx = nchunk.x;
            acc[8*m+0] += prev * w.x + c.x * w.z;
            acc[8*m+1] += c.x  * w.y + c.y * w.w;
            acc[8*m+2] += c.x  * w.x + c.y * w.z;
            acc[8*m+3] += c.y  * w.y + c.z * w.w;
            acc[8*m+4] += c.y  * w.x + c.z * w.z;
            acc[8*m+5] += c.z  * w.y + c.w * w.w;
            acc[8*m+6] += c.z  * w.x + c.w * w.z;
            acc[8*m+7] += c.w  * w.y + nx  * w.w;
            prev = c.w;
            c = nchunk;
        }
        w = wn;
    }

    float* yr = yout + co * SOUT;
#pragma unroll
    for (int m = 0; m < LOUT / 4; ++m) {
        float4 v;
        v.x = act ? leaky(acc[4*m+0]) : acc[4*m+0];
        v.y = act ? leaky(acc[4*m+1]) : acc[4*m+1];
        v.z = act ? leaky(acc[4*m+2]) : acc[4*m+2];
        v.w = act ? leaky(acc[4*m+3]) : acc[4*m+3];
        *(float4*)(yr + 4*m) = v;
    }
}

__global__ void __launch_bounds__(128, 4) npg_kernel(
    const float* __restrict__ x,    const float* __restrict__ noise,
    const float* __restrict__ Wup,  const float* __restrict__ bup,
    const float* __restrict__ Wd0,  const float* __restrict__ bd0,
    const float* __restrict__ Wd1,  const float* __restrict__ bd1,
    const float* __restrict__ Wd2,  const float* __restrict__ bd2,
    const float* __restrict__ Wdo,  const float* __restrict__ bdo,
    const float* __restrict__ Wc0,  const float* __restrict__ bc0,
    const float* __restrict__ Wc1,  const float* __restrict__ bc1,
    const float* __restrict__ Wc2,  const float* __restrict__ bc2,
    const float* __restrict__ Wc3,  const float* __restrict__ bc3,
    float* __restrict__ out)
{
    extern __shared__ float smem[];
    float* A    = smem + A_OFF;
    float* B    = smem + B_OFF;
    float* xf   = smem + XF_OFF;
    float* vseq = smem + VS_OFF;
    __shared__ float s_red[4];
    __shared__ float s_decay;

    const int row  = blockIdx.x;
    const int t    = threadIdx.x;
    const int lane = t & 31;
    const int warp = t >> 5;

    xf[t] = x[row * DCH + t];
    __syncthreads();

    // ---------------- decay head: 3x (D->D leaky) -> D->1 sigmoid ----------------
    {
        float* h0 = A;
        float* h1 = A + DCH;
        h0[t] = xf[t];
        __syncthreads();
        const float* Ws[3] = {Wd0, Wd1, Wd2};
        const float* bs[3] = {bd0, bd1, bd2};
        float* cur = h0;
        float* nxt = h1;
        for (int L = 0; L < 3; ++L) {
            const float* W = Ws[L];
            float s0 = 0.f, s1 = 0.f, s2 = 0.f, s3 = 0.f;
#pragma unroll 4
            for (int dd = 0; dd < DCH; dd += 4) {
                s0 += cur[dd+0] * W[(dd+0) * DCH + t];
                s1 += cur[dd+1] * W[(dd+1) * DCH + t];
                s2 += cur[dd+2] * W[(dd+2) * DCH + t];
                s3 += cur[dd+3] * W[(dd+3) * DCH + t];
            }
            float a = bs[L][t] + ((s0 + s1) + (s2 + s3));
            nxt[t] = leaky(a);
            __syncthreads();
            float* tmp = cur; cur = nxt; nxt = tmp;
        }
        float p = cur[t] * Wdo[t];
#pragma unroll
        for (int off = 16; off > 0; off >>= 1) p += __shfl_xor_sync(0xffffffffu, p, off);
        if (lane == 0) s_red[warp] = p;
        __syncthreads();
        if (t == 0) {
            float s = s_red[0] + s_red[1] + s_red[2] + s_red[3] + bdo[0];
            s_decay = 0.8f + 0.2f / (1.f + expf(-s));
        }
        __syncthreads();
    }

    // ---------------- up projection: xf @ Wup -> [128][8] into A (stride 12) -----
    {
        float a[8];
        {
            float4 b0 = *(const float4*)(bup + t * 8);
            float4 b1 = *(const float4*)(bup + t * 8 + 4);
            a[0]=b0.x; a[1]=b0.y; a[2]=b0.z; a[3]=b0.w;
            a[4]=b1.x; a[5]=b1.y; a[6]=b1.z; a[7]=b1.w;
        }
        const float* wr = Wup + t * 8;
        float4 c0 = *(const float4*)(wr);
        float4 c1 = *(const float4*)(wr + 4);
#pragma unroll 1
        for (int dd = 0; dd < DCH; ++dd) {
            float4 n0 = c0, n1 = c1;
            if (dd + 1 < DCH) {
                n0 = *(const float4*)(wr + (dd + 1) * (DCH * 8));
                n1 = *(const float4*)(wr + (dd + 1) * (DCH * 8) + 4);
            }
            float xv = xf[dd];
            a[0] += xv * c0.x; a[1] += xv * c0.y; a[2] += xv * c0.z; a[3] += xv * c0.w;
            a[4] += xv * c1.x; a[5] += xv * c1.y; a[6] += xv * c1.z; a[7] += xv * c1.w;
            c0 = n0; c1 = n1;
        }
        __syncthreads();   // decay phase fully done with A
        float4 o0 = make_float4(a[0], a[1], a[2], a[3]);
        float4 o1 = make_float4(a[4], a[5], a[6], a[7]);
        *(float4*)(A + t * 12)     = o0;
        *(float4*)(A + t * 12 + 4) = o1;
        __syncthreads();
    }

    // ---------------- transposed conv stack: 8 -> 16 -> 32 -> 64 -----------------
    tconv<8,  12, 20>(Wc0, bc0, A, B, t, true);
    __syncthreads();
    tconv<16, 20, 36>(Wc1, bc1, B, A, t, true);
    __syncthreads();
    tconv<32, 36, 68>(Wc2, bc2, A, B, t, true);
    __syncthreads();

    // ---------------- final tconv to 1 channel (64 -> 128), square ---------------
    {
        const int  o  = t;
        const int  j  = o >> 1;
        const bool ev = (o & 1) == 0;
        const int  ia = ev ? (j - 1) : j;
        const int  ib = ev ? j : (j + 1);
        const bool va = ia >= 0;
        const bool vb = ib <= 63;
        float acc = bc3[0];
        float4 w = *(const float4*)(Wc3);
#pragma unroll 1
        for (int ci = 0; ci < DCH; ++ci) {
            float4 wn = w;
            if (ci + 1 < DCH) wn = *(const float4*)(Wc3 + ((ci + 1) << 2));
            const float* xr = B + ci * 68;
            float xa = va ? xr[ia] : 0.f;
            float xb = vb ? xr[ib] : 0.f;
            float ca = ev ? w.x : w.y;
            float cb = ev ? w.z : w.w;
            acc += xa * ca + xb * cb;
            w = wn;
        }
        vseq[t] = acc * acc;
    }
    __syncthreads();

    // ---------------- exponential decay recurrence: warp-parallel scan -----------
    if (warp == 0) {
        const float d = s_decay;
        float4 u = *(const float4*)(vseq + lane * 4);
        float p0 = u.x;
        float p1 = fmaf(d, p0, u.y);
        float p2 = fmaf(d, p1, u.z);
        float p3 = fmaf(d, p2, u.w);
        const float d2 = d * d;
        const float d4 = d2 * d2;
        float V = p3;
        float m = d4;
#pragma unroll
        for (int off = 1; off < 32; off <<= 1) {
            float up = __shfl_up_sync(0xffffffffu, V, off);
            if (lane >= off) V = fmaf(m, up, V);
            m = m * m;
        }
        float C = __shfl_up_sync(0xffffffffu, V, 1);
        if (lane == 0) C = 0.f;
        float4 o;
        o.x = fmaf(C, d,      p0);
        o.y = fmaf(C, d2,     p1);
        o.z = fmaf(C, d2 * d, p2);
        o.w = fmaf(C, d4,     p3);
        *(float4*)(vseq + lane * 4) = o;
    }
    __syncthreads();

    // ---------------- linear interp 128 -> 32768, multiply by noise --------------
    {
        const float4* np_ = (const float4*)(noise + (size_t)row * NS);
        float4*       op  = (float4*)(out + (size_t)row * NS);
#pragma unroll 4
        for (int i4 = t; i4 < NS / 4; i4 += 128) {
            float4 nz = np_[i4];
            int n0 = i4 << 2;
            float4 r;
#pragma unroll
            for (int k = 0; k < 4; ++k) {
                // pos = (n+0.5)/256 - 0.5 = n/256 - 0.498046875 (exact in fp32)
                float pos = fmaf((float)(n0 + k), 0.00390625f, -0.498046875f);
                pos = fminf(fmaxf(pos, 0.f), 127.f);
                int   i0 = (int)pos;
                float w  = pos - (float)i0;
                int   i1 = min(i0 + 1, NF - 1);
                float val = vseq[i0] * (1.f - w) + vseq[i1] * w;
                ((float*)&r)[k] = val * ((const float*)&nz)[k];
            }
            op[i4] = r;
        }
    }
}

extern "C" void kernel_launch(void* const* d_in, const int* in_sizes, int n_in,
                              void* d_out, int out_size)
{
    (void)in_sizes; (void)n_in; (void)out_size;
    const float* x    = (const float*)d_in[0];
    const float* noise= (const float*)d_in[1];
    const float* Wup  = (const float*)d_in[2];
    const float* bup  = (const float*)d_in[3];
    const float* Wd0  = (const float*)d_in[4];
    const float* bd0  = (const float*)d_in[5];
    const float* Wd1  = (const float*)d_in[6];
    const float* bd1  = (const float*)d_in[7];
    const float* Wd2  = (const float*)d_in[8];
    const float* bd2  = (const float*)d_in[9];
    const float* Wdo  = (const float*)d_in[10];
    const float* bdo  = (const float*)d_in[11];
    const float* Wc0  = (const float*)d_in[12];
    const float* bc0  = (const float*)d_in[13];
    const float* Wc1  = (const float*)d_in[14];
    const float* bc1  = (const float*)d_in[15];
    const float* Wc2  = (const float*)d_in[16];
    const float* bc2  = (const float*)d_in[17];
    const float* Wc3  = (const float*)d_in[18];
    const float* bc3  = (const float*)d_in[19];
    float* out = (float*)d_out;

    cudaFuncSetAttribute(npg_kernel, cudaFuncAttributeMaxDynamicSharedMemorySize, SMEM_BYTES);
    npg_kernel<<<BE, 128, SMEM_BYTES>>>(
        x, noise, Wup, bup, Wd0, bd0, Wd1, bd1, Wd2, bd2, Wdo, bdo,
        Wc0, bc0, Wc1, bc1, Wc2, bc2, Wc3, bc3, out);
}

// round 3
// speedup vs baseline: 1.3599x; 1.3599x over previous
#include <cuda_runtime.h>
#include <math.h>

#define DCH   128
#define BE    1024
#define NF    128
#define NS    32768
#define NT    256      // threads per CTA

// Dynamic smem (floats)
#define A_OFF   0
#define A_SIZE  (128*36)
#define B_OFF   (A_OFF + A_SIZE)
#define B_SIZE  (128*68)
#define XF_OFF  (B_OFF + B_SIZE)
#define VS_OFF  (XF_OFF + 128)
#define PART_OFF (VS_OFF + 128)
#define SMEM_FLOATS (PART_OFF + 256)
#define SMEM_BYTES  (SMEM_FLOATS * 4)

__device__ __forceinline__ float leaky(float v) { return v > 0.f ? v : 0.2f * v; }

// Transposed conv (k=4, s=2, p=1), JAX conv_transpose (no flip):
//   y[2j]   = sum_ci x[j-1]*w0 + x[j]*w2
//   y[2j+1] = sum_ci x[j]  *w1 + x[j+1]*w3
// Thread (co, h): computes output positions [h*LIN, (h+1)*LIN) of row co.
template <int LIN, int SIN, int SOUT>
__device__ __forceinline__ void tconv(
    const float* __restrict__ W, const float* __restrict__ bias,
    const float* __restrict__ xin, float* __restrict__ yout,
    int co, int h, bool act)
{
    constexpr int NJ = LIN / 2;          // j positions per thread
    constexpr int NC = NJ / 4;           // float4 chunks per thread
    float acc[LIN];                      // outputs per thread
    const float bv = bias[co];
#pragma unroll
    for (int l = 0; l < LIN; ++l) acc[l] = bv;

    const int j0 = h * NJ;

    for (int ci = 0; ci < DCH; ++ci) {
        float4 w = *(const float4*)(W + ((ci * DCH + co) << 2));
        const float* xr = xin + ci * SIN + j0;
        float prev = (h == 0) ? 0.f : xr[-1];
        float xend = (h == 1) ? 0.f : xr[NJ];
        const float4* xv = (const float4*)xr;
        float4 c = xv[0];
#pragma unroll
        for (int m = 0; m < NC; ++m) {
            float nx;
            float4 cn;
            if (m + 1 < NC) { cn = xv[m + 1]; nx = cn.x; }
            else            { cn = c;         nx = xend; }
            acc[8*m+0] += prev * w.x + c.x * w.z;
            acc[8*m+1] += c.x  * w.y + c.y * w.w;
            acc[8*m+2] += c.x  * w.x + c.y * w.z;
            acc[8*m+3] += c.y  * w.y + c.z * w.w;
            acc[8*m+4] += c.y  * w.x + c.z * w.z;
            acc[8*m+5] += c.z  * w.y + c.w * w.w;
            acc[8*m+6] += c.z  * w.x + c.w * w.z;
            acc[8*m+7] += c.w  * w.y + nx  * w.w;
            prev = c.w;
            c = cn;
        }
    }

    float* yr = yout + co * SOUT + 2 * j0;   // 2*j0 = h*LIN, multiple of 4
#pragma unroll
    for (int m = 0; m < LIN / 4; ++m) {
        float4 v;
        v.x = act ? leaky(acc[4*m+0]) : acc[4*m+0];
        v.y = act ? leaky(acc[4*m+1]) : acc[4*m+1];
        v.z = act ? leaky(acc[4*m+2]) : acc[4*m+2];
        v.w = act ? leaky(acc[4*m+3]) : acc[4*m+3];
        *(float4*)(yr + 4*m) = v;
    }
}

__global__ void __launch_bounds__(NT, 3) npg_kernel(
    const float* __restrict__ x,    const float* __restrict__ noise,
    const float* __restrict__ Wup,  const float* __restrict__ bup,
    const float* __restrict__ Wd0,  const float* __restrict__ bd0,
    const float* __restrict__ Wd1,  const float* __restrict__ bd1,
    const float* __restrict__ Wd2,  const float* __restrict__ bd2,
    const float* __restrict__ Wdo,  const float* __restrict__ bdo,
    const float* __restrict__ Wc0,  const float* __restrict__ bc0,
    const float* __restrict__ Wc1,  const float* __restrict__ bc1,
    const float* __restrict__ Wc2,  const float* __restrict__ bc2,
    const float* __restrict__ Wc3,  const float* __restrict__ bc3,
    float* __restrict__ out)
{
    extern __shared__ float smem[];
    float* A    = smem + A_OFF;
    float* B    = smem + B_OFF;
    float* xf   = smem + XF_OFF;
    float* vseq = smem + VS_OFF;
    float* part = smem + PART_OFF;
    __shared__ float s_decay;

    const int row  = blockIdx.x;
    const int t    = threadIdx.x;
    const int lane = t & 31;
    const int warp = t >> 5;
    const int co   = t & 127;
    const int h    = t >> 7;

    if (t < DCH) xf[t] = x[row * DCH + t];
    __syncthreads();

    // ---------------- decay head: 3x (D->D leaky) -> D->1 sigmoid ----------------
    // ci-split across halves, smem reduce.
    {
        float* h0 = A;
        float* h1 = A + DCH;
        if (t < DCH) h0[t] = xf[t];
        __syncthreads();
        const float* Ws[3] = {Wd0, Wd1, Wd2};
        const float* bs[3] = {bd0, bd1, bd2};
        float* cur = h0;
        float* nxt = h1;
        for (int L = 0; L < 3; ++L) {
            const float* W = Ws[L];
            const int d0 = h * 64;
            float s0 = 0.f, s1 = 0.f, s2 = 0.f, s3 = 0.f;
            for (int dd = d0; dd < d0 + 64; dd += 4) {
                s0 += cur[dd+0] * W[(dd+0) * DCH + co];
                s1 += cur[dd+1] * W[(dd+1) * DCH + co];
                s2 += cur[dd+2] * W[(dd+2) * DCH + co];
                s3 += cur[dd+3] * W[(dd+3) * DCH + co];
            }
            part[t] = (s0 + s1) + (s2 + s3);
            __syncthreads();
            if (t < DCH) nxt[t] = leaky(bs[L][t] + part[t] + part[t + 128]);
            __syncthreads();
            float* tmp = cur; cur = nxt; nxt = tmp;
        }
        // dot(cur, Wdo): each of the 256 threads handles 0/1 element; block reduce
        float p = (t < DCH) ? cur[t] * Wdo[t] : 0.f;
#pragma unroll
        for (int off = 16; off > 0; off >>= 1) p += __shfl_xor_sync(0xffffffffu, p, off);
        if (lane == 0) part[warp] = p;
        __syncthreads();
        if (t == 0) {
            float s = bdo[0];
            for (int wgi = 0; wgi < NT / 32; ++wgi) s += part[wgi];
            s_decay = 0.8f + 0.2f / (1.f + expf(-s));
        }
        __syncthreads();
    }

    // ---------------- up projection: xf @ Wup -> [128][8] into A (stride 12) -----
    // thread (co, h) computes output columns [4h, 4h+4)
    {
        float4 a = *(const float4*)(bup + co * 8 + 4 * h);
        const float* wr = Wup + co * 8 + 4 * h;
        for (int dd = 0; dd < DCH; ++dd) {
            float4 w = *(const float4*)(wr + dd * (DCH * 8));
            float xv = xf[dd];
            a.x += xv * w.x; a.y += xv * w.y; a.z += xv * w.z; a.w += xv * w.w;
        }
        __syncthreads();   // decay phase fully done with A
        *(float4*)(A + co * 12 + 4 * h) = a;
        __syncthreads();
    }

    // ---------------- transposed conv stack: 8 -> 16 -> 32 -> 64 -----------------
    tconv<8,  12, 20>(Wc0, bc0, A, B, co, h, true);
    __syncthreads();
    tconv<16, 20, 36>(Wc1, bc1, B, A, co, h, true);
    __syncthreads();
    tconv<32, 36, 68>(Wc2, bc2, A, B, co, h, true);
    __syncthreads();

    // ---------------- final tconv to 1 channel (64 -> 128), square ---------------
    // position = co, ci-split across halves, smem reduce.
    {
        const int  p  = co;
        const int  j  = p >> 1;
        const bool ev = (p & 1) == 0;
        const int  ia = ev ? (j - 1) : j;
        const int  ib = ev ? j : (j + 1);
        const bool va = ia >= 0;
        const bool vb = ib <= 63;
        const int  c0 = h * 64;
        float acc = 0.f;
        for (int ci = c0; ci < c0 + 64; ++ci) {
            float4 w = *(const float4*)(Wc3 + (ci << 2));
            const float* xr = B + ci * 68;
            float xa = va ? xr[ia] : 0.f;
            float xb = vb ? xr[ib] : 0.f;
            float ca = ev ? w.x : w.y;
            float cb = ev ? w.z : w.w;
            acc += xa * ca + xb * cb;
        }
        part[t] = acc;
        __syncthreads();
        if (t < NF) {
            float v = bc3[0] + part[t] + part[t + 128];
            vseq[t] = v * v;
        }
    }
    __syncthreads();

    // ---------------- exponential decay recurrence: warp scan --------------------
    if (warp == 0) {
        const float d = s_decay;
        float4 u = *(const float4*)(vseq + lane * 4);
        float p0 = u.x;
        float p1 = fmaf(d, p0, u.y);
        float p2 = fmaf(d, p1, u.z);
        float p3 = fmaf(d, p2, u.w);
        const float d2 = d * d;
        const float d4 = d2 * d2;
        float V = p3;
        float m = d4;
#pragma unroll
        for (int off = 1; off < 32; off <<= 1) {
            float up = __shfl_up_sync(0xffffffffu, V, off);
            if (lane >= off) V = fmaf(m, up, V);
            m = m * m;
        }
        float C = __shfl_up_sync(0xffffffffu, V, 1);
        if (lane == 0) C = 0.f;
        float4 o;
        o.x = fmaf(C, d,      p0);
        o.y = fmaf(C, d2,     p1);
        o.z = fmaf(C, d2 * d, p2);
        o.w = fmaf(C, d4,     p3);
        *(float4*)(vseq + lane * 4) = o;
    }
    __syncthreads();

    // ---------------- linear interp 128 -> 32768, multiply by noise --------------
    {
        const float4* np_ = (const float4*)(noise + (size_t)row * NS);
        float4*       op  = (float4*)(out + (size_t)row * NS);
#pragma unroll 4
        for (int i4 = t; i4 < NS / 4; i4 += NT) {
            float4 nz = np_[i4];
            int n0 = i4 << 2;
            float4 r;
#pragma unroll
            for (int k = 0; k < 4; ++k) {
                float pos = fmaf((float)(n0 + k), 0.00390625f, -0.498046875f);
                pos = fminf(fmaxf(pos, 0.f), 127.f);
                int   i0 = (int)pos;
                float w  = pos - (float)i0;
                int   i1 = min(i0 + 1, NF - 1);
                float val = vseq[i0] * (1.f - w) + vseq[i1] * w;
                ((float*)&r)[k] = val * ((const float*)&nz)[k];
            }
            op[i4] = r;
        }
    }
}

extern "C" void kernel_launch(void* const* d_in, const int* in_sizes, int n_in,
                              void* d_out, int out_size)
{
    (void)in_sizes; (void)n_in; (void)out_size;
    const float* x    = (const float*)d_in[0];
    const float* noise= (const float*)d_in[1];
    const float* Wup  = (const float*)d_in[2];
    const float* bup  = (const float*)d_in[3];
    const float* Wd0  = (const float*)d_in[4];
    const float* bd0  = (const float*)d_in[5];
    const float* Wd1  = (const float*)d_in[6];
    const float* bd1  = (const float*)d_in[7];
    const float* Wd2  = (const float*)d_in[8];
    const float* bd2  = (const float*)d_in[9];
    const float* Wdo  = (const float*)d_in[10];
    const float* bdo  = (const float*)d_in[11];
    const float* Wc0  = (const float*)d_in[12];
    const float* bc0  = (const float*)d_in[13];
    const float* Wc1  = (const float*)d_in[14];
    const float* bc1  = (const float*)d_in[15];
    const float* Wc2  = (const float*)d_in[16];
    const float* bc2  = (const float*)d_in[17];
    const float* Wc3  = (const float*)d_in[18];
    const float* bc3  = (const float*)d_in[19];
    float* out = (float*)d_out;

    cudaFuncSetAttribute(npg_kernel, cudaFuncAttributeMaxDynamicSharedMemorySize, SMEM_BYTES);
    npg_kernel<<<BE, NT, SMEM_BYTES>>>(
        x, noise, Wup, bup, Wd0, bd0, Wd1, bd1, Wd2, bd2, Wdo, bdo,
        Wc0, bc0, Wc1, bc1, Wc2, bc2, Wc3, bc3, out);
}

// round 4
// speedup vs baseline: 1.9535x; 1.4365x over previous
#include <cuda_runtime.h>
#include <math.h>

#define DCH   128
#define BE    1024
#define NF    128
#define NS    32768
#define NT    256      // threads per CTA

// Dynamic smem (floats)
#define A_OFF    0
#define A_SIZE   (128*36)
#define B_OFF    (A_OFF + A_SIZE)
#define B_SIZE   (128*68)
#define XF_OFF   (B_OFF + B_SIZE)
#define VS_OFF   (XF_OFF + 128)
#define DV_OFF   (VS_OFF + 128)
#define PART_OFF (DV_OFF + 128)
#define SMEM_FLOATS (PART_OFF + 256)
#define SMEM_BYTES  (SMEM_FLOATS * 4)

typedef unsigned long long u64;

__device__ __forceinline__ float leaky(float v) { return v > 0.f ? v : 0.2f * v; }

// Packed f32x2 helpers (sm_100+): exact fp32 per lane, 2 MACs per issue slot.
__device__ __forceinline__ u64 pk(float a, float b) {
    u64 r; asm("mov.b64 %0, {%1,%2};" : "=l"(r) : "f"(a), "f"(b)); return r;
}
__device__ __forceinline__ void upk(u64 v, float& a, float& b) {
    asm("mov.b64 {%0,%1}, %2;" : "=f"(a), "=f"(b) : "l"(v));
}
__device__ __forceinline__ void f2fma(u64& d, u64 a, u64 b) {
    asm("fma.rn.f32x2 %0, %1, %2, %0;" : "+l"(d) : "l"(a), "l"(b));
}

// Transposed conv (k=4, s=2, p=1), JAX conv_transpose (no flip):
//   y[2j]   = sum_ci x[j-1]*w0 + x[j]*w2
//   y[2j+1] = sum_ci x[j]  *w1 + x[j+1]*w3
// Packed: acc2[j] = (y[2j], y[2j+1]);
//   acc2[j] += (x[j-1],x[j])*(w0,w1);  acc2[j] += (x[j],x[j+1])*(w2,w3)
// Thread (co, h) computes output positions [h*LIN, (h+1)*LIN) of row co.
template <int LIN, int SIN, int SOUT>
__device__ __forceinline__ void tconv(
    const float* __restrict__ W, const float* __restrict__ bias,
    const float* __restrict__ xin, float* __restrict__ yout,
    int co, int h, bool act)
{
    constexpr int NJ = LIN / 2;          // j positions (=output pairs) per thread
    constexpr int NC = NJ / 4;           // float4 x-chunks per thread
    const float bv = bias[co];
    u64 acc[NJ];
    {
        u64 bp = pk(bv, bv);
#pragma unroll
        for (int j = 0; j < NJ; ++j) acc[j] = bp;
    }
    const int j0 = h * NJ;

    for (int ci = 0; ci < DCH; ++ci) {
        float4 w = *(const float4*)(W + ((ci * DCH + co) << 2));
        u64 w01 = pk(w.x, w.y);          // adjacent regs from LDG.128 -> free pair
        u64 w23 = pk(w.z, w.w);
        const float* xr = xin + ci * SIN + j0;
        float prev = (h == 0) ? 0.f : xr[-1];
        float xend = (h == 1) ? 0.f : xr[NJ];
        const float4* xv = (const float4*)xr;
        float4 c = xv[0];
        u64 p0 = pk(prev, c.x);
#pragma unroll
        for (int m = 0; m < NC; ++m) {
            float nx; float4 cn;
            if (m + 1 < NC) { cn = xv[m + 1]; nx = cn.x; }
            else            { cn = c;         nx = xend; }
            u64 p1 = pk(c.x, c.y);
            u64 p2 = pk(c.y, c.z);
            u64 p3 = pk(c.z, c.w);
            u64 p4 = pk(c.w, nx);
            f2fma(acc[4*m+0], p0, w01); f2fma(acc[4*m+0], p1, w23);
            f2fma(acc[4*m+1], p1, w01); f2fma(acc[4*m+1], p2, w23);
            f2fma(acc[4*m+2], p2, w01); f2fma(acc[4*m+2], p3, w23);
            f2fma(acc[4*m+3], p3, w01); f2fma(acc[4*m+3], p4, w23);
            p0 = p4;
            c = cn;
        }
    }

    float* yr = yout + co * SOUT + 2 * j0;   // 2*j0 multiple of 4
#pragma unroll
    for (int m = 0; m < NJ / 2; ++m) {
        float a0, a1, b0, b1;
        upk(acc[2*m],   a0, a1);
        upk(acc[2*m+1], b0, b1);
        float4 v;
        v.x = act ? leaky(a0) : a0;
        v.y = act ? leaky(a1) : a1;
        v.z = act ? leaky(b0) : b0;
        v.w = act ? leaky(b1) : b1;
        *(float4*)(yr + 4*m) = v;
    }
}

__global__ void __launch_bounds__(NT, 3) npg_kernel(
    const float* __restrict__ x,    const float* __restrict__ noise,
    const float* __restrict__ Wup,  const float* __restrict__ bup,
    const float* __restrict__ Wd0,  const float* __restrict__ bd0,
    const float* __restrict__ Wd1,  const float* __restrict__ bd1,
    const float* __restrict__ Wd2,  const float* __restrict__ bd2,
    const float* __restrict__ Wdo,  const float* __restrict__ bdo,
    const float* __restrict__ Wc0,  const float* __restrict__ bc0,
    const float* __restrict__ Wc1,  const float* __restrict__ bc1,
    const float* __restrict__ Wc2,  const float* __restrict__ bc2,
    const float* __restrict__ Wc3,  const float* __restrict__ bc3,
    float* __restrict__ out)
{
    extern __shared__ float smem[];
    float* A    = smem + A_OFF;
    float* B    = smem + B_OFF;
    float* xf   = smem + XF_OFF;
    float* vseq = smem + VS_OFF;
    float* dv   = smem + DV_OFF;
    float* part = smem + PART_OFF;
    __shared__ float s_decay;

    const int row  = blockIdx.x;
    const int t    = threadIdx.x;
    const int lane = t & 31;
    const int warp = t >> 5;
    const int co   = t & 127;
    const int h    = t >> 7;

    if (t < DCH) xf[t] = x[row * DCH + t];
    __syncthreads();

    // ---------------- decay head: 3x (D->D leaky) -> D->1 sigmoid ----------------
    {
        float* h0 = A;
        float* h1 = A + DCH;
        if (t < DCH) h0[t] = xf[t];
        __syncthreads();
        const float* Ws[3] = {Wd0, Wd1, Wd2};
        const float* bs[3] = {bd0, bd1, bd2};
        float* cur = h0;
        float* nxt = h1;
        for (int L = 0; L < 3; ++L) {
            const float* W = Ws[L];
            const int d0 = h * 64;
            float s0 = 0.f, s1 = 0.f, s2 = 0.f, s3 = 0.f;
            for (int dd = d0; dd < d0 + 64; dd += 4) {
                s0 += cur[dd+0] * W[(dd+0) * DCH + co];
                s1 += cur[dd+1] * W[(dd+1) * DCH + co];
                s2 += cur[dd+2] * W[(dd+2) * DCH + co];
                s3 += cur[dd+3] * W[(dd+3) * DCH + co];
            }
            part[t] = (s0 + s1) + (s2 + s3);
            __syncthreads();
            if (t < DCH) nxt[t] = leaky(bs[L][t] + part[t] + part[t + 128]);
            __syncthreads();
            float* tmp = cur; cur = nxt; nxt = tmp;
        }
        float p = (t < DCH) ? cur[t] * Wdo[t] : 0.f;
#pragma unroll
        for (int off = 16; off > 0; off >>= 1) p += __shfl_xor_sync(0xffffffffu, p, off);
        if (lane == 0) part[warp] = p;
        __syncthreads();
        if (t == 0) {
            float s = bdo[0];
            for (int wgi = 0; wgi < NT / 32; ++wgi) s += part[wgi];
            s_decay = 0.8f + 0.2f / (1.f + expf(-s));
        }
        __syncthreads();
    }

    // ---------------- up projection: xf @ Wup -> [128][8] into A (stride 12) -----
    // thread (co, h) computes output columns [4h, 4h+4); packed f32x2 accum.
    {
        float4 bvv = *(const float4*)(bup + co * 8 + 4 * h);
        u64 a01 = pk(bvv.x, bvv.y);
        u64 a23 = pk(bvv.z, bvv.w);
        const float* wr = Wup + co * 8 + 4 * h;
        for (int dd = 0; dd < DCH; ++dd) {
            float4 w = *(const float4*)(wr + dd * (DCH * 8));
            float xvv = xf[dd];
            u64 xx = pk(xvv, xvv);
            f2fma(a01, xx, pk(w.x, w.y));
            f2fma(a23, xx, pk(w.z, w.w));
        }
        __syncthreads();   // decay phase fully done with A
        float4 o;
        upk(a01, o.x, o.y);
        upk(a23, o.z, o.w);
        *(float4*)(A + co * 12 + 4 * h) = o;
        __syncthreads();
    }

    // ---------------- transposed conv stack: 8 -> 16 -> 32 -> 64 -----------------
    tconv<8,  12, 20>(Wc0, bc0, A, B, co, h, true);
    __syncthreads();
    tconv<16, 20, 36>(Wc1, bc1, B, A, co, h, true);
    __syncthreads();
    tconv<32, 36, 68>(Wc2, bc2, A, B, co, h, true);
    __syncthreads();

    // ---------------- final tconv to 1 channel (64 -> 128), square ---------------
    {
        const int  p  = co;
        const int  j  = p >> 1;
        const bool ev = (p & 1) == 0;
        const int  ia = ev ? (j - 1) : j;
        const int  ib = ev ? j : (j + 1);
        const bool va = ia >= 0;
        const bool vb = ib <= 63;
        const int  c0 = h * 64;
        float acc = 0.f;
        for (int ci = c0; ci < c0 + 64; ++ci) {
            float4 w = *(const float4*)(Wc3 + (ci << 2));
            const float* xr = B + ci * 68;
            float xa = va ? xr[ia] : 0.f;
            float xb = vb ? xr[ib] : 0.f;
            float ca = ev ? w.x : w.y;
            float cb = ev ? w.z : w.w;
            acc += xa * ca + xb * cb;
        }
        part[t] = acc;
        __syncthreads();
        if (t < NF) {
            float v = bc3[0] + part[t] + part[t + 128];
            vseq[t] = v * v;
        }
    }
    __syncthreads();

    // ---------------- exponential decay recurrence: warp scan --------------------
    if (warp == 0) {
        const float d = s_decay;
        float4 u = *(const float4*)(vseq + lane * 4);
        float p0 = u.x;
        float p1 = fmaf(d, p0, u.y);
        float p2 = fmaf(d, p1, u.z);
        float p3 = fmaf(d, p2, u.w);
        const float d2 = d * d;
        const float d4 = d2 * d2;
        float V = p3;
        float m = d4;
#pragma unroll
        for (int off = 1; off < 32; off <<= 1) {
            float up = __shfl_up_sync(0xffffffffu, V, off);
            if (lane >= off) V = fmaf(m, up, V);
            m = m * m;
        }
        float C = __shfl_up_sync(0xffffffffu, V, 1);
        if (lane == 0) C = 0.f;
        float4 o;
        o.x = fmaf(C, d,      p0);
        o.y = fmaf(C, d2,     p1);
        o.z = fmaf(C, d2 * d, p2);
        o.w = fmaf(C, d4,     p3);
        *(float4*)(vseq + lane * 4) = o;
    }
    __syncthreads();
    // slope per frame: dv[f] = v[f+1]-v[f]; dv[127]=0 makes the i1-clamp implicit
    if (t < NF) dv[t] = (t < NF - 1) ? (vseq[t + 1] - vseq[t]) : 0.f;
    __syncthreads();

    // ---------------- linear interp 128 -> 32768, multiply by noise --------------
    {
        const float4* np_ = (const float4*)(noise + (size_t)row * NS);
        float4*       op  = (float4*)(out + (size_t)row * NS);
#pragma unroll 4
        for (int i4 = t; i4 < NS / 4; i4 += NT) {
            float4 nz = np_[i4];
            int n0 = i4 << 2;
            float4 r;
#pragma unroll
            for (int k = 0; k < 4; ++k) {
                float pos = fmaf((float)(n0 + k), 0.00390625f, -0.498046875f);
                pos = fminf(fmaxf(pos, 0.f), 127.f);
                int   i0 = (int)pos;
                float w  = pos - (float)i0;
                float val = fmaf(w, dv[i0], vseq[i0]);
                ((float*)&r)[k] = val * ((const float*)&nz)[k];
            }
            op[i4] = r;
        }
    }
}

extern "C" void kernel_launch(void* const* d_in, const int* in_sizes, int n_in,
                              void* d_out, int out_size)
{
    (void)in_sizes; (void)n_in; (void)out_size;
    const float* x    = (const float*)d_in[0];
    const float* noise= (const float*)d_in[1];
    const float* Wup  = (const float*)d_in[2];
    const float* bup  = (const float*)d_in[3];
    const float* Wd0  = (const float*)d_in[4];
    const float* bd0  = (const float*)d_in[5];
    const float* Wd1  = (const float*)d_in[6];
    const float* bd1  = (const float*)d_in[7];
    const float* Wd2  = (const float*)d_in[8];
    const float* bd2  = (const float*)d_in[9];
    const float* Wdo  = (const float*)d_in[10];
    const float* bdo  = (const float*)d_in[11];
    const float* Wc0  = (const float*)d_in[12];
    const float* bc0  = (const float*)d_in[13];
    const float* Wc1  = (const float*)d_in[14];
    const float* bc1  = (const float*)d_in[15];
    const float* Wc2  = (const float*)d_in[16];
    const float* bc2  = (const float*)d_in[17];
    const float* Wc3  = (const float*)d_in[18];
    const float* bc3  = (const float*)d_in[19];
    float* out = (float*)d_out;

    cudaFuncSetAttribute(npg_kernel, cudaFuncAttributeMaxDynamicSharedMemorySize, SMEM_BYTES);
    npg_kernel<<<BE, NT, SMEM_BYTES>>>(
        x, noise, Wup, bup, Wd0, bd0, Wd1, bd1, Wd2, bd2, Wdo, bdo,
        Wc0, bc0, Wc1, bc1, Wc2, bc2, Wc3, bc3, out);
}